// round 15
// baseline (speedup 1.0000x reference)
#include <cuda_runtime.h>
#include <cuda_fp16.h>
#include <math.h>
#include <stdint.h>

// LTCAttentionCell — round 15: main kernel = R12 verbatim (at the legacy-HMMA
// issue floor: 255K cyc). Prep rewritten for MLP=8 (32 elems/thread, 8
// independent LDG.128 -> 16 cvt -> 4 STG.128): R12 prep was latency-bound
// (DRAM=51%, HBM floor for its 95MB is ~6us).

#define IN_DIM 128
#define HID    512
#define ATT    256
#define KTOT   896
#define BROWS  16384

#define BM 128
#define BN 64
#define KBLK 128
#define NTH 512
#define A_SZ  32768              // 128 rows x 256B
#define B_SZ  16384              // 64 rows x 256B
#define STAGE_BYTES (A_SZ + 3 * B_SZ)        // 81920
#define SMEM_DYN (2 * STAGE_BYTES + 128)     // ~160K

__device__ __half g_comb[(size_t)BROWS * KTOT];
__device__ __half g_wgd [(size_t)1024  * KTOT];
__device__ __half g_wtau[(size_t)512   * HID];

__device__ __forceinline__ uint32_t s2u(const void* p) {
    return (uint32_t)__cvta_generic_to_shared(p);
}
__device__ __forceinline__ void cp16(uint32_t dst, const void* src) {
    asm volatile("cp.async.cg.shared.global [%0], [%1], 16;" :: "r"(dst), "l"(src));
}
__device__ __forceinline__ void cp_commit() {
    asm volatile("cp.async.commit_group;" ::: "memory");
}
template<int N> __device__ __forceinline__ void cp_wait() {
    asm volatile("cp.async.wait_group %0;" :: "n"(N) : "memory");
}
__device__ __forceinline__ void ldm_x4(uint32_t* d, uint32_t addr) {
    asm volatile("ldmatrix.sync.aligned.m8n8.x4.shared.b16 {%0,%1,%2,%3}, [%4];"
                 : "=r"(d[0]), "=r"(d[1]), "=r"(d[2]), "=r"(d[3]) : "r"(addr));
}
__device__ __forceinline__ void mma_f16(float* c, const uint32_t* a, uint32_t b0, uint32_t b1) {
    asm volatile("mma.sync.aligned.m16n8k16.row.col.f32.f16.f16.f32 "
                 "{%0,%1,%2,%3}, {%4,%5,%6,%7}, {%8,%9}, {%0,%1,%2,%3};"
                 : "+f"(c[0]), "+f"(c[1]), "+f"(c[2]), "+f"(c[3])
                 : "r"(a[0]), "r"(a[1]), "r"(a[2]), "r"(a[3]), "r"(b0), "r"(b1));
}

// ---- fast-math activations (err ~1e-6 << 1.7e-4 fp16 floor) ----
__device__ __forceinline__ float softplus_fast(float x) {
    return (x > 20.0f) ? x : __logf(1.0f + __expf(x));
}
__device__ __forceinline__ float sigmoid_fast(float x) {
    return __fdividef(1.0f, 1.0f + __expf(-x));
}
__device__ __forceinline__ float tanh_fast(float x) {
    return 1.0f - __fdividef(2.0f, __expf(2.0f * x) + 1.0f);
}

// 256B rows = 16x16B chunks; swizzle low 3 bits of chunk with row&7
__device__ __forceinline__ uint32_t sw256(int row, int k) {
    int ch = k >> 3;
    int swc = ((ch & 7) ^ (row & 7)) | (ch & 8);
    return row * 256 + ((swc << 4) | ((k & 7) * 2));
}

// ---------------- high-ILP pre-pass: 32 elems/thread, MLP=8 ----------------
__device__ __forceinline__ void cvt32(const float* __restrict__ src,
                                      __half* __restrict__ dst) {
    float4 v[8];
#pragma unroll
    for (int i = 0; i < 8; ++i)
        v[i] = *reinterpret_cast<const float4*>(src + i * 4);   // 8 independent LDG.128
    uint4 o[4];
#pragma unroll
    for (int i = 0; i < 4; ++i) {
        __half2 h0 = __floats2half2_rn(v[2*i].x,   v[2*i].y);
        __half2 h1 = __floats2half2_rn(v[2*i].z,   v[2*i].w);
        __half2 h2 = __floats2half2_rn(v[2*i+1].x, v[2*i+1].y);
        __half2 h3 = __floats2half2_rn(v[2*i+1].z, v[2*i+1].w);
        o[i].x = *reinterpret_cast<uint32_t*>(&h0);
        o[i].y = *reinterpret_cast<uint32_t*>(&h1);
        o[i].z = *reinterpret_cast<uint32_t*>(&h2);
        o[i].w = *reinterpret_cast<uint32_t*>(&h3);
    }
#pragma unroll
    for (int i = 0; i < 4; ++i)
        *reinterpret_cast<uint4*>(dst + i * 8) = o[i];
}

__global__ void __launch_bounds__(256)
prep_all(const float* __restrict__ h_ltc, const float* __restrict__ x_t,
         const float* __restrict__ context, const float* __restrict__ W_gd,
         const float* __restrict__ W_tau)
{
    int idx = blockIdx.x * 256 + threadIdx.x;
    if (idx < 458752) {                      // combined: 16384 rows x 28 chunks
        int m = idx / 28;
        int j = (idx - m * 28) * 32;
        const float* src;
        if (j < IN_DIM)            src = x_t     + (size_t)m * IN_DIM + j;
        else if (j < IN_DIM + HID) src = h_ltc   + (size_t)m * HID    + (j - IN_DIM);
        else                       src = context + (size_t)m * ATT    + (j - IN_DIM - HID);
        cvt32(src, &g_comb[(size_t)m * KTOT + j]);
    } else if (idx < 487424) {               // W_gd: 1024 rows x 28 chunks
        int e = idx - 458752;
        int row = e / 28;
        int j = (e - row * 28) * 32;
        cvt32(&W_gd[(size_t)row * KTOT + j], &g_wgd[(size_t)row * KTOT + j]);
    } else {                                 // W_tau: 512 rows x 16 chunks
        int e = idx - 487424;
        int row = e >> 4;
        int j = (e & 15) * 32;
        cvt32(&W_tau[(size_t)row * HID + j], &g_wtau[(size_t)row * HID + j]);
    }
}

// ---------------- main kernel (R12 verbatim) ----------------
__global__ void __launch_bounds__(NTH, 1)
ltc_f16_kernel(const float* __restrict__ h_ltc, const float* __restrict__ b_gd,
               const float* __restrict__ b_tau, const float* __restrict__ gleak,
               const float* __restrict__ cm, float* __restrict__ out)
{
    extern __shared__ char smem[];
    const uint32_t data = (s2u(smem) + 127) & ~127u;

    const int tid  = threadIdx.x;
    const int wid  = tid >> 5;
    const int lane = tid & 31;
    const int m0 = blockIdx.y * BM;
    const int n0 = blockIdx.x * BN;

    const int wm = (wid & 3) * 32;    // 4 m-warps x 4 n-warps, warp tile 32x16
    const int wn = (wid >> 2) * 16;

    const int a_row = ((lane >> 3) & 1) * 8 + (lane & 7);
    const int a_k   = ((lane >> 4) & 1) * 8;
    const int b_row = ((lane >> 4) & 1) * 8 + (lane & 7);
    const int b_k   = ((lane >> 3) & 1) * 8;

    uint32_t aoff[2][4], bgof[4];
#pragma unroll
    for (int ks = 0; ks < 4; ++ks) {
#pragma unroll
        for (int mb = 0; mb < 2; ++mb)
            aoff[mb][ks] = sw256(wm + mb * 16 + a_row, ks * 16 + a_k);
        bgof[ks] = A_SZ + sw256(wn + b_row, ks * 16 + b_k);
    }

    uint32_t dAo[4]; const __half* srcA[4];
#pragma unroll
    for (int i = 0; i < 4; ++i) {
        int s = tid + i * 512, r = s >> 4, ch = s & 15;
        dAo[i] = sw256(r, ch * 8);
        srcA[i] = g_comb + (size_t)(m0 + r) * KTOT + ch * 8;
    }
    uint32_t dBo[2]; const __half *srcG[2], *srcD[2], *srcT[2];
#pragma unroll
    for (int i = 0; i < 2; ++i) {
        int s = tid + i * 512, r = s >> 4, ch = s & 15;
        dBo[i] = sw256(r, ch * 8);
        srcG[i] = g_wgd  + (size_t)(n0 + r) * KTOT + ch * 8;
        srcD[i] = g_wgd  + (size_t)(HID + n0 + r) * KTOT + ch * 8;
        srcT[i] = g_wtau + (size_t)(n0 + r) * HID + ch * 8;
    }

    float accg[2][2][4] = {}, accd[2][2][4] = {}, acct[2][2][4] = {};

    auto load_chunk = [&](int c, uint32_t st) {
#pragma unroll
        for (int i = 0; i < 4; ++i)
            cp16(st + dAo[i], srcA[i] + c * KBLK);
#pragma unroll
        for (int i = 0; i < 2; ++i) {
            cp16(st + A_SZ + dBo[i],        srcG[i] + c * KBLK);
            cp16(st + A_SZ + B_SZ + dBo[i], srcD[i] + c * KBLK);
        }
        if (c >= 1 && c < 5) {
#pragma unroll
            for (int i = 0; i < 2; ++i)
                cp16(st + A_SZ + 2 * B_SZ + dBo[i], srcT[i] + (c - 1) * KBLK);
        }
        cp_commit();
    };

    auto compute = [&](uint32_t st, bool tau_act) {
#pragma unroll
        for (int k8 = 0; k8 < 8; ++k8) {
            const int ks = k8 & 3;
            const uint32_t ext = (k8 >> 2) * 128;
            uint32_t a[2][4];
            ldm_x4(a[0], st + aoff[0][ks] + ext);
            ldm_x4(a[1], st + aoff[1][ks] + ext);
            uint32_t bg[4], bd[4], bt[4];
            const uint32_t bga = st + bgof[ks] + ext;
            ldm_x4(bg, bga);
            ldm_x4(bd, bga + B_SZ);
            if (tau_act) ldm_x4(bt, bga + 2 * B_SZ);
#pragma unroll
            for (int mb = 0; mb < 2; ++mb)
#pragma unroll
                for (int nb = 0; nb < 2; ++nb) {
                    mma_f16(accg[mb][nb], a[mb], bg[nb * 2], bg[nb * 2 + 1]);
                    mma_f16(accd[mb][nb], a[mb], bd[nb * 2], bd[nb * 2 + 1]);
                }
            if (tau_act) {
#pragma unroll
                for (int mb = 0; mb < 2; ++mb)
#pragma unroll
                    for (int nb = 0; nb < 2; ++nb)
                        mma_f16(acct[mb][nb], a[mb], bt[nb * 2], bt[nb * 2 + 1]);
            }
        }
    };

    const uint32_t st0 = data;
    const uint32_t st1 = data + STAGE_BYTES;

    load_chunk(0, st0);

    cp_wait<0>(); __syncthreads();
    load_chunk(1, st1);
    compute(st0, false);          // c=0

    cp_wait<0>(); __syncthreads();
    load_chunk(2, st0);
    compute(st1, true);           // c=1

    cp_wait<0>(); __syncthreads();
    load_chunk(3, st1);
    compute(st0, true);           // c=2

    cp_wait<0>(); __syncthreads();
    load_chunk(4, st0);
    compute(st1, true);           // c=3

    cp_wait<0>(); __syncthreads();
    load_chunk(5, st1);
    compute(st0, true);           // c=4

    cp_wait<0>(); __syncthreads();
    load_chunk(6, st0);
    compute(st1, false);          // c=5

    cp_wait<0>(); __syncthreads();
    compute(st0, false);          // c=6

    // ---- fused epilogue (fast math) ----
    const int g  = lane >> 2;
    const int c2 = (lane & 3) * 2;
#pragma unroll
    for (int mb = 0; mb < 2; ++mb)
#pragma unroll
        for (int nb = 0; nb < 2; ++nb) {
            const int n = n0 + wn + nb * 8 + c2;
            const float bg0 = __ldg(&b_gd[n]),        bg1 = __ldg(&b_gd[n + 1]);
            const float bd0 = __ldg(&b_gd[n + HID]),  bd1 = __ldg(&b_gd[n + HID + 1]);
            const float bt0 = __ldg(&b_tau[n]),       bt1 = __ldg(&b_tau[n + 1]);
            const float dc0 = softplus_fast(__ldg(&cm[n]))   + softplus_fast(__ldg(&gleak[n]))   + 1e-6f;
            const float dc1 = softplus_fast(__ldg(&cm[n+1])) + softplus_fast(__ldg(&gleak[n+1])) + 1e-6f;
#pragma unroll
            for (int h = 0; h < 2; ++h) {
                const int m = m0 + wm + mb * 16 + h * 8 + g;
                const float2 hl = *reinterpret_cast<const float2*>(&h_ltc[(size_t)m * HID + n]);

                float gate0 = accg[mb][nb][h * 2 + 0] + bg0;
                float gate1 = accg[mb][nb][h * 2 + 1] + bg1;
                float dyn0  = accd[mb][nb][h * 2 + 0] + bd0;
                float dyn1  = accd[mb][nb][h * 2 + 1] + bd1;
                float tau0  = softplus_fast(acct[mb][nb][h * 2 + 0] + bt0);
                float tau1  = softplus_fast(acct[mb][nb][h * 2 + 1] + bt1);

                float r0 = __fdividef(sigmoid_fast(gate0) * tanh_fast(dyn0) - hl.x, tau0 + dc0);
                float r1 = __fdividef(sigmoid_fast(gate1) * tanh_fast(dyn1) - hl.y, tau1 + dc1);

                float2 o; o.x = r0; o.y = r1;
                *reinterpret_cast<float2*>(&out[(size_t)m * HID + n]) = o;
            }
        }
}

extern "C" void kernel_launch(void* const* d_in, const int* in_sizes, int n_in,
                              void* d_out, int out_size)
{
    // input order: t, h_ltc, x_t, context, W_gd, b_gd, W_tau, b_tau, gleak, cm
    const float* h_ltc   = (const float*)d_in[1];
    const float* x_t     = (const float*)d_in[2];
    const float* context = (const float*)d_in[3];
    const float* W_gd    = (const float*)d_in[4];
    const float* b_gd    = (const float*)d_in[5];
    const float* W_tau   = (const float*)d_in[6];
    const float* b_tau   = (const float*)d_in[7];
    const float* gleak   = (const float*)d_in[8];
    const float* cm      = (const float*)d_in[9];
    float* out = (float*)d_out;

    cudaFuncSetAttribute(ltc_f16_kernel,
                         cudaFuncAttributeMaxDynamicSharedMemorySize, SMEM_DYN);

    // 458752 (combined) + 28672 (W_gd) + 8192 (W_tau) = 495616 threads
    prep_all<<<1936, 256>>>(h_ltc, x_t, context, W_gd, W_tau);

    dim3 grid(HID / BN, BROWS / BM);   // (8, 128)
    ltc_f16_kernel<<<grid, NTH, SMEM_DYN>>>(h_ltc, b_gd, b_tau, gleak, cm, out);
}

// round 16
// speedup vs baseline: 1.0289x; 1.0289x over previous
#include <cuda_runtime.h>
#include <cuda_fp16.h>
#include <math.h>
#include <stdint.h>

// LTCAttentionCell — round 16: main kernel = R12 verbatim (at legacy-HMMA issue
// floor, 9.45M MMA / 592 SMSP x 16cyc = 255K cyc ~= 128us). Prep v3: coalesced
// (32B/lane units, lane-consecutive) AND high-MLP (4 block-strided units per
// thread = 8 independent LDG.128). R15's prep broke coalescing; this keeps it.

#define IN_DIM 128
#define HID    512
#define ATT    256
#define KTOT   896
#define BROWS  16384

#define BM 128
#define BN 64
#define KBLK 128
#define NTH 512
#define A_SZ  32768              // 128 rows x 256B
#define B_SZ  16384              // 64 rows x 256B
#define STAGE_BYTES (A_SZ + 3 * B_SZ)        // 81920
#define SMEM_DYN (2 * STAGE_BYTES + 128)     // ~160K

__device__ __half g_comb[(size_t)BROWS * KTOT];
__device__ __half g_wgd [(size_t)1024  * KTOT];
__device__ __half g_wtau[(size_t)512   * HID];

__device__ __forceinline__ uint32_t s2u(const void* p) {
    return (uint32_t)__cvta_generic_to_shared(p);
}
__device__ __forceinline__ void cp16(uint32_t dst, const void* src) {
    asm volatile("cp.async.cg.shared.global [%0], [%1], 16;" :: "r"(dst), "l"(src));
}
__device__ __forceinline__ void cp_commit() {
    asm volatile("cp.async.commit_group;" ::: "memory");
}
template<int N> __device__ __forceinline__ void cp_wait() {
    asm volatile("cp.async.wait_group %0;" :: "n"(N) : "memory");
}
__device__ __forceinline__ void ldm_x4(uint32_t* d, uint32_t addr) {
    asm volatile("ldmatrix.sync.aligned.m8n8.x4.shared.b16 {%0,%1,%2,%3}, [%4];"
                 : "=r"(d[0]), "=r"(d[1]), "=r"(d[2]), "=r"(d[3]) : "r"(addr));
}
__device__ __forceinline__ void mma_f16(float* c, const uint32_t* a, uint32_t b0, uint32_t b1) {
    asm volatile("mma.sync.aligned.m16n8k16.row.col.f32.f16.f16.f32 "
                 "{%0,%1,%2,%3}, {%4,%5,%6,%7}, {%8,%9}, {%0,%1,%2,%3};"
                 : "+f"(c[0]), "+f"(c[1]), "+f"(c[2]), "+f"(c[3])
                 : "r"(a[0]), "r"(a[1]), "r"(a[2]), "r"(a[3]), "r"(b0), "r"(b1));
}

// ---- fast-math activations (err ~1e-6 << 1.7e-4 fp16 floor) ----
__device__ __forceinline__ float softplus_fast(float x) {
    return (x > 20.0f) ? x : __logf(1.0f + __expf(x));
}
__device__ __forceinline__ float sigmoid_fast(float x) {
    return __fdividef(1.0f, 1.0f + __expf(-x));
}
__device__ __forceinline__ float tanh_fast(float x) {
    return 1.0f - __fdividef(2.0f, __expf(2.0f * x) + 1.0f);
}

// 256B rows = 16x16B chunks; swizzle low 3 bits of chunk with row&7
__device__ __forceinline__ uint32_t sw256(int row, int k) {
    int ch = k >> 3;
    int swc = ((ch & 7) ^ (row & 7)) | (ch & 8);
    return row * 256 + ((swc << 4) | ((k & 7) * 2));
}

// ---------------- prep v3: coalesced + MLP=8 ----------------
// cvt8 units (8 elems = 32B src, 16B dst). Units:
//   [0, 1835008)           combined: m = u/112, j = (u%112)*8
//   [1835008, 1949696)     W_gd:     row = e/112, j = (e%112)*8
//   [1949696, 1982464)     W_tau:    row = e>>6,  j = (e&63)*8
#define U_COMB 1835008
#define U_WGD  1949696
#define U_TOT  1982464

__global__ void __launch_bounds__(256)
prep_all(const float* __restrict__ h_ltc, const float* __restrict__ x_t,
         const float* __restrict__ context, const float* __restrict__ W_gd,
         const float* __restrict__ W_tau)
{
    const int base = blockIdx.x * 1024 + threadIdx.x;
    const float* s[4];
    __half* d[4];
#pragma unroll
    for (int k = 0; k < 4; ++k) {
        int u = base + k * 256;            // lane-consecutive within each k
        if (u < U_COMB) {
            int m = u / 112;
            int j = (u - m * 112) * 8;
            if (j < IN_DIM)            s[k] = x_t     + (size_t)m * IN_DIM + j;
            else if (j < IN_DIM + HID) s[k] = h_ltc   + (size_t)m * HID    + (j - IN_DIM);
            else                       s[k] = context + (size_t)m * ATT    + (j - IN_DIM - HID);
            d[k] = &g_comb[(size_t)m * KTOT + j];
        } else if (u < U_WGD) {
            int e = u - U_COMB;
            int row = e / 112;
            int j = (e - row * 112) * 8;
            s[k] = &W_gd[(size_t)row * KTOT + j];
            d[k] = &g_wgd[(size_t)row * KTOT + j];
        } else {
            int e = u - U_WGD;
            int row = e >> 6;
            int j = (e & 63) * 8;
            s[k] = &W_tau[(size_t)row * HID + j];
            d[k] = &g_wtau[(size_t)row * HID + j];
        }
    }
    // 8 independent loads first (MLP=8), then convert + store
    float4 v[8];
#pragma unroll
    for (int k = 0; k < 4; ++k) {
        v[2 * k]     = *reinterpret_cast<const float4*>(s[k]);
        v[2 * k + 1] = *reinterpret_cast<const float4*>(s[k] + 4);
    }
#pragma unroll
    for (int k = 0; k < 4; ++k) {
        __half2 h0 = __floats2half2_rn(v[2*k].x,   v[2*k].y);
        __half2 h1 = __floats2half2_rn(v[2*k].z,   v[2*k].w);
        __half2 h2 = __floats2half2_rn(v[2*k+1].x, v[2*k+1].y);
        __half2 h3 = __floats2half2_rn(v[2*k+1].z, v[2*k+1].w);
        uint4 o;
        o.x = *reinterpret_cast<uint32_t*>(&h0);
        o.y = *reinterpret_cast<uint32_t*>(&h1);
        o.z = *reinterpret_cast<uint32_t*>(&h2);
        o.w = *reinterpret_cast<uint32_t*>(&h3);
        *reinterpret_cast<uint4*>(d[k]) = o;
    }
}

// ---------------- main kernel (R12 verbatim) ----------------
__global__ void __launch_bounds__(NTH, 1)
ltc_f16_kernel(const float* __restrict__ h_ltc, const float* __restrict__ b_gd,
               const float* __restrict__ b_tau, const float* __restrict__ gleak,
               const float* __restrict__ cm, float* __restrict__ out)
{
    extern __shared__ char smem[];
    const uint32_t data = (s2u(smem) + 127) & ~127u;

    const int tid  = threadIdx.x;
    const int wid  = tid >> 5;
    const int lane = tid & 31;
    const int m0 = blockIdx.y * BM;
    const int n0 = blockIdx.x * BN;

    const int wm = (wid & 3) * 32;    // 4 m-warps x 4 n-warps, warp tile 32x16
    const int wn = (wid >> 2) * 16;

    const int a_row = ((lane >> 3) & 1) * 8 + (lane & 7);
    const int a_k   = ((lane >> 4) & 1) * 8;
    const int b_row = ((lane >> 4) & 1) * 8 + (lane & 7);
    const int b_k   = ((lane >> 3) & 1) * 8;

    uint32_t aoff[2][4], bgof[4];
#pragma unroll
    for (int ks = 0; ks < 4; ++ks) {
#pragma unroll
        for (int mb = 0; mb < 2; ++mb)
            aoff[mb][ks] = sw256(wm + mb * 16 + a_row, ks * 16 + a_k);
        bgof[ks] = A_SZ + sw256(wn + b_row, ks * 16 + b_k);
    }

    uint32_t dAo[4]; const __half* srcA[4];
#pragma unroll
    for (int i = 0; i < 4; ++i) {
        int s = tid + i * 512, r = s >> 4, ch = s & 15;
        dAo[i] = sw256(r, ch * 8);
        srcA[i] = g_comb + (size_t)(m0 + r) * KTOT + ch * 8;
    }
    uint32_t dBo[2]; const __half *srcG[2], *srcD[2], *srcT[2];
#pragma unroll
    for (int i = 0; i < 2; ++i) {
        int s = tid + i * 512, r = s >> 4, ch = s & 15;
        dBo[i] = sw256(r, ch * 8);
        srcG[i] = g_wgd  + (size_t)(n0 + r) * KTOT + ch * 8;
        srcD[i] = g_wgd  + (size_t)(HID + n0 + r) * KTOT + ch * 8;
        srcT[i] = g_wtau + (size_t)(n0 + r) * HID + ch * 8;
    }

    float accg[2][2][4] = {}, accd[2][2][4] = {}, acct[2][2][4] = {};

    auto load_chunk = [&](int c, uint32_t st) {
#pragma unroll
        for (int i = 0; i < 4; ++i)
            cp16(st + dAo[i], srcA[i] + c * KBLK);
#pragma unroll
        for (int i = 0; i < 2; ++i) {
            cp16(st + A_SZ + dBo[i],        srcG[i] + c * KBLK);
            cp16(st + A_SZ + B_SZ + dBo[i], srcD[i] + c * KBLK);
        }
        if (c >= 1 && c < 5) {
#pragma unroll
            for (int i = 0; i < 2; ++i)
                cp16(st + A_SZ + 2 * B_SZ + dBo[i], srcT[i] + (c - 1) * KBLK);
        }
        cp_commit();
    };

    auto compute = [&](uint32_t st, bool tau_act) {
#pragma unroll
        for (int k8 = 0; k8 < 8; ++k8) {
            const int ks = k8 & 3;
            const uint32_t ext = (k8 >> 2) * 128;
            uint32_t a[2][4];
            ldm_x4(a[0], st + aoff[0][ks] + ext);
            ldm_x4(a[1], st + aoff[1][ks] + ext);
            uint32_t bg[4], bd[4], bt[4];
            const uint32_t bga = st + bgof[ks] + ext;
            ldm_x4(bg, bga);
            ldm_x4(bd, bga + B_SZ);
            if (tau_act) ldm_x4(bt, bga + 2 * B_SZ);
#pragma unroll
            for (int mb = 0; mb < 2; ++mb)
#pragma unroll
                for (int nb = 0; nb < 2; ++nb) {
                    mma_f16(accg[mb][nb], a[mb], bg[nb * 2], bg[nb * 2 + 1]);
                    mma_f16(accd[mb][nb], a[mb], bd[nb * 2], bd[nb * 2 + 1]);
                }
            if (tau_act) {
#pragma unroll
                for (int mb = 0; mb < 2; ++mb)
#pragma unroll
                    for (int nb = 0; nb < 2; ++nb)
                        mma_f16(acct[mb][nb], a[mb], bt[nb * 2], bt[nb * 2 + 1]);
            }
        }
    };

    const uint32_t st0 = data;
    const uint32_t st1 = data + STAGE_BYTES;

    load_chunk(0, st0);

    cp_wait<0>(); __syncthreads();
    load_chunk(1, st1);
    compute(st0, false);          // c=0

    cp_wait<0>(); __syncthreads();
    load_chunk(2, st0);
    compute(st1, true);           // c=1

    cp_wait<0>(); __syncthreads();
    load_chunk(3, st1);
    compute(st0, true);           // c=2

    cp_wait<0>(); __syncthreads();
    load_chunk(4, st0);
    compute(st1, true);           // c=3

    cp_wait<0>(); __syncthreads();
    load_chunk(5, st1);
    compute(st0, true);           // c=4

    cp_wait<0>(); __syncthreads();
    load_chunk(6, st0);
    compute(st1, false);          // c=5

    cp_wait<0>(); __syncthreads();
    compute(st0, false);          // c=6

    // ---- fused epilogue (fast math) ----
    const int g  = lane >> 2;
    const int c2 = (lane & 3) * 2;
#pragma unroll
    for (int mb = 0; mb < 2; ++mb)
#pragma unroll
        for (int nb = 0; nb < 2; ++nb) {
            const int n = n0 + wn + nb * 8 + c2;
            const float bg0 = __ldg(&b_gd[n]),        bg1 = __ldg(&b_gd[n + 1]);
            const float bd0 = __ldg(&b_gd[n + HID]),  bd1 = __ldg(&b_gd[n + HID + 1]);
            const float bt0 = __ldg(&b_tau[n]),       bt1 = __ldg(&b_tau[n + 1]);
            const float dc0 = softplus_fast(__ldg(&cm[n]))   + softplus_fast(__ldg(&gleak[n]))   + 1e-6f;
            const float dc1 = softplus_fast(__ldg(&cm[n+1])) + softplus_fast(__ldg(&gleak[n+1])) + 1e-6f;
#pragma unroll
            for (int h = 0; h < 2; ++h) {
                const int m = m0 + wm + mb * 16 + h * 8 + g;
                const float2 hl = *reinterpret_cast<const float2*>(&h_ltc[(size_t)m * HID + n]);

                float gate0 = accg[mb][nb][h * 2 + 0] + bg0;
                float gate1 = accg[mb][nb][h * 2 + 1] + bg1;
                float dyn0  = accd[mb][nb][h * 2 + 0] + bd0;
                float dyn1  = accd[mb][nb][h * 2 + 1] + bd1;
                float tau0  = softplus_fast(acct[mb][nb][h * 2 + 0] + bt0);
                float tau1  = softplus_fast(acct[mb][nb][h * 2 + 1] + bt1);

                float r0 = __fdividef(sigmoid_fast(gate0) * tanh_fast(dyn0) - hl.x, tau0 + dc0);
                float r1 = __fdividef(sigmoid_fast(gate1) * tanh_fast(dyn1) - hl.y, tau1 + dc1);

                float2 o; o.x = r0; o.y = r1;
                *reinterpret_cast<float2*>(&out[(size_t)m * HID + n]) = o;
            }
        }
}

extern "C" void kernel_launch(void* const* d_in, const int* in_sizes, int n_in,
                              void* d_out, int out_size)
{
    // input order: t, h_ltc, x_t, context, W_gd, b_gd, W_tau, b_tau, gleak, cm
    const float* h_ltc   = (const float*)d_in[1];
    const float* x_t     = (const float*)d_in[2];
    const float* context = (const float*)d_in[3];
    const float* W_gd    = (const float*)d_in[4];
    const float* b_gd    = (const float*)d_in[5];
    const float* W_tau   = (const float*)d_in[6];
    const float* b_tau   = (const float*)d_in[7];
    const float* gleak   = (const float*)d_in[8];
    const float* cm      = (const float*)d_in[9];
    float* out = (float*)d_out;

    cudaFuncSetAttribute(ltc_f16_kernel,
                         cudaFuncAttributeMaxDynamicSharedMemorySize, SMEM_DYN);

    // U_TOT = 1982464 units / 4 per thread / 256 per block = 1936 blocks
    prep_all<<<1936, 256>>>(h_ltc, x_t, context, W_gd, W_tau);

    dim3 grid(HID / BN, BROWS / BM);   // (8, 128)
    ltc_f16_kernel<<<grid, NTH, SMEM_DYN>>>(h_ltc, b_gd, b_tau, gleak, cm, out);
}

// round 17
// speedup vs baseline: 1.1066x; 1.0755x over previous
#include <cuda_runtime.h>
#include <cuda_fp16.h>
#include <math.h>
#include <stdint.h>

// LTCAttentionCell — round 17: R12 exact (main at legacy-HMMA issue floor
// ~255K cyc; prep at its 95MB HBM floor ~12us) + epilogue operand prefetch:
// during the last chunk's MMAs, cp.async the h_ltc tile (32KB) and bias arrays
// (1.25KB) into the idle stage-1 smem; epilogue reads at LDS latency.

#define IN_DIM 128
#define HID    512
#define ATT    256
#define KTOT   896
#define BROWS  16384

#define BM 128
#define BN 64
#define KBLK 128
#define NTH 512
#define A_SZ  32768              // 128 rows x 256B
#define B_SZ  16384              // 64 rows x 256B
#define STAGE_BYTES (A_SZ + 3 * B_SZ)        // 81920
#define SMEM_DYN (2 * STAGE_BYTES + 128)     // ~160K

__device__ __half g_comb[(size_t)BROWS * KTOT];
__device__ __half g_wgd [(size_t)1024  * KTOT];
__device__ __half g_wtau[(size_t)512   * HID];

__device__ __forceinline__ uint32_t s2u(const void* p) {
    return (uint32_t)__cvta_generic_to_shared(p);
}
__device__ __forceinline__ void cp16(uint32_t dst, const void* src) {
    asm volatile("cp.async.cg.shared.global [%0], [%1], 16;" :: "r"(dst), "l"(src));
}
__device__ __forceinline__ void cp_commit() {
    asm volatile("cp.async.commit_group;" ::: "memory");
}
template<int N> __device__ __forceinline__ void cp_wait() {
    asm volatile("cp.async.wait_group %0;" :: "n"(N) : "memory");
}
__device__ __forceinline__ void ldm_x4(uint32_t* d, uint32_t addr) {
    asm volatile("ldmatrix.sync.aligned.m8n8.x4.shared.b16 {%0,%1,%2,%3}, [%4];"
                 : "=r"(d[0]), "=r"(d[1]), "=r"(d[2]), "=r"(d[3]) : "r"(addr));
}
__device__ __forceinline__ void mma_f16(float* c, const uint32_t* a, uint32_t b0, uint32_t b1) {
    asm volatile("mma.sync.aligned.m16n8k16.row.col.f32.f16.f16.f32 "
                 "{%0,%1,%2,%3}, {%4,%5,%6,%7}, {%8,%9}, {%0,%1,%2,%3};"
                 : "+f"(c[0]), "+f"(c[1]), "+f"(c[2]), "+f"(c[3])
                 : "r"(a[0]), "r"(a[1]), "r"(a[2]), "r"(a[3]), "r"(b0), "r"(b1));
}

// ---- fast-math activations (err ~1e-6 << 1.7e-4 fp16 floor) ----
__device__ __forceinline__ float softplus_fast(float x) {
    return (x > 20.0f) ? x : __logf(1.0f + __expf(x));
}
__device__ __forceinline__ float sigmoid_fast(float x) {
    return __fdividef(1.0f, 1.0f + __expf(-x));
}
__device__ __forceinline__ float tanh_fast(float x) {
    return 1.0f - __fdividef(2.0f, __expf(2.0f * x) + 1.0f);
}

// 256B rows = 16x16B chunks; swizzle low 3 bits of chunk with row&7
__device__ __forceinline__ uint32_t sw256(int row, int k) {
    int ch = k >> 3;
    int swc = ((ch & 7) ^ (row & 7)) | (ch & 8);
    return row * 256 + ((swc << 4) | ((k & 7) * 2));
}

// ---------------- fused pre-pass (R12 verbatim: at HBM floor) ----------------
__global__ void __launch_bounds__(256)
prep_all(const float* __restrict__ h_ltc, const float* __restrict__ x_t,
         const float* __restrict__ context, const float* __restrict__ W_gd,
         const float* __restrict__ W_tau)
{
    if (blockIdx.x < 7168) {
        int idx = blockIdx.x * 256 + threadIdx.x;   // 16384 * 112
        int m = idx / 112;
        int j = (idx - m * 112) * 8;
        const float* src;
        if (j < IN_DIM)            src = x_t     + (size_t)m * IN_DIM + j;
        else if (j < IN_DIM + HID) src = h_ltc   + (size_t)m * HID    + (j - IN_DIM);
        else                       src = context + (size_t)m * ATT    + (j - IN_DIM - HID);
        float4 v0 = *reinterpret_cast<const float4*>(src);
        float4 v1 = *reinterpret_cast<const float4*>(src + 4);
        __half2 h0 = __floats2half2_rn(v0.x, v0.y);
        __half2 h1 = __floats2half2_rn(v0.z, v0.w);
        __half2 h2 = __floats2half2_rn(v1.x, v1.y);
        __half2 h3 = __floats2half2_rn(v1.z, v1.w);
        uint4 o;
        o.x = *reinterpret_cast<uint32_t*>(&h0);
        o.y = *reinterpret_cast<uint32_t*>(&h1);
        o.z = *reinterpret_cast<uint32_t*>(&h2);
        o.w = *reinterpret_cast<uint32_t*>(&h3);
        *reinterpret_cast<uint4*>(&g_comb[(size_t)m * KTOT + j]) = o;
    } else {
        int idx = (blockIdx.x - 7168) * 256 + threadIdx.x;  // 114688 + 32768
        const float* src; __half* dst;
        if (idx < 114688) {
            int row = idx / 112;
            int j = (idx - row * 112) * 8;
            src = &W_gd[(size_t)row * KTOT + j];
            dst = &g_wgd[(size_t)row * KTOT + j];
        } else {
            int e = idx - 114688;
            int row = e >> 6;
            int j = (e & 63) * 8;
            src = &W_tau[(size_t)row * HID + j];
            dst = &g_wtau[(size_t)row * HID + j];
        }
        float4 v0 = *reinterpret_cast<const float4*>(src);
        float4 v1 = *reinterpret_cast<const float4*>(src + 4);
        __half2 h0 = __floats2half2_rn(v0.x, v0.y);
        __half2 h1 = __floats2half2_rn(v0.z, v0.w);
        __half2 h2 = __floats2half2_rn(v1.x, v1.y);
        __half2 h3 = __floats2half2_rn(v1.z, v1.w);
        uint4 o;
        o.x = *reinterpret_cast<uint32_t*>(&h0);
        o.y = *reinterpret_cast<uint32_t*>(&h1);
        o.z = *reinterpret_cast<uint32_t*>(&h2);
        o.w = *reinterpret_cast<uint32_t*>(&h3);
        *reinterpret_cast<uint4*>(dst) = o;
    }
}

// ---------------- main kernel (R12 + epilogue prefetch) ----------------
__global__ void __launch_bounds__(NTH, 1)
ltc_f16_kernel(const float* __restrict__ h_ltc, const float* __restrict__ b_gd,
               const float* __restrict__ b_tau, const float* __restrict__ gleak,
               const float* __restrict__ cm, float* __restrict__ out)
{
    extern __shared__ char smem[];
    const uint32_t data = (s2u(smem) + 127) & ~127u;
    char* dptr = smem + (data - s2u(smem));

    const int tid  = threadIdx.x;
    const int wid  = tid >> 5;
    const int lane = tid & 31;
    const int m0 = blockIdx.y * BM;
    const int n0 = blockIdx.x * BN;

    const int wm = (wid & 3) * 32;    // 4 m-warps x 4 n-warps, warp tile 32x16
    const int wn = (wid >> 2) * 16;

    const int a_row = ((lane >> 3) & 1) * 8 + (lane & 7);
    const int a_k   = ((lane >> 4) & 1) * 8;
    const int b_row = ((lane >> 4) & 1) * 8 + (lane & 7);
    const int b_k   = ((lane >> 3) & 1) * 8;

    uint32_t aoff[2][4], bgof[4];
#pragma unroll
    for (int ks = 0; ks < 4; ++ks) {
#pragma unroll
        for (int mb = 0; mb < 2; ++mb)
            aoff[mb][ks] = sw256(wm + mb * 16 + a_row, ks * 16 + a_k);
        bgof[ks] = A_SZ + sw256(wn + b_row, ks * 16 + b_k);
    }

    uint32_t dAo[4]; const __half* srcA[4];
#pragma unroll
    for (int i = 0; i < 4; ++i) {
        int s = tid + i * 512, r = s >> 4, ch = s & 15;
        dAo[i] = sw256(r, ch * 8);
        srcA[i] = g_comb + (size_t)(m0 + r) * KTOT + ch * 8;
    }
    uint32_t dBo[2]; const __half *srcG[2], *srcD[2], *srcT[2];
#pragma unroll
    for (int i = 0; i < 2; ++i) {
        int s = tid + i * 512, r = s >> 4, ch = s & 15;
        dBo[i] = sw256(r, ch * 8);
        srcG[i] = g_wgd  + (size_t)(n0 + r) * KTOT + ch * 8;
        srcD[i] = g_wgd  + (size_t)(HID + n0 + r) * KTOT + ch * 8;
        srcT[i] = g_wtau + (size_t)(n0 + r) * HID + ch * 8;
    }

    float accg[2][2][4] = {}, accd[2][2][4] = {}, acct[2][2][4] = {};

    auto load_chunk = [&](int c, uint32_t st) {
#pragma unroll
        for (int i = 0; i < 4; ++i)
            cp16(st + dAo[i], srcA[i] + c * KBLK);
#pragma unroll
        for (int i = 0; i < 2; ++i) {
            cp16(st + A_SZ + dBo[i],        srcG[i] + c * KBLK);
            cp16(st + A_SZ + B_SZ + dBo[i], srcD[i] + c * KBLK);
        }
        if (c >= 1 && c < 5) {
#pragma unroll
            for (int i = 0; i < 2; ++i)
                cp16(st + A_SZ + 2 * B_SZ + dBo[i], srcT[i] + (c - 1) * KBLK);
        }
        cp_commit();
    };

    auto compute = [&](uint32_t st, bool tau_act) {
#pragma unroll
        for (int k8 = 0; k8 < 8; ++k8) {
            const int ks = k8 & 3;
            const uint32_t ext = (k8 >> 2) * 128;
            uint32_t a[2][4];
            ldm_x4(a[0], st + aoff[0][ks] + ext);
            ldm_x4(a[1], st + aoff[1][ks] + ext);
            uint32_t bg[4], bd[4], bt[4];
            const uint32_t bga = st + bgof[ks] + ext;
            ldm_x4(bg, bga);
            ldm_x4(bd, bga + B_SZ);
            if (tau_act) ldm_x4(bt, bga + 2 * B_SZ);
#pragma unroll
            for (int mb = 0; mb < 2; ++mb)
#pragma unroll
                for (int nb = 0; nb < 2; ++nb) {
                    mma_f16(accg[mb][nb], a[mb], bg[nb * 2], bg[nb * 2 + 1]);
                    mma_f16(accd[mb][nb], a[mb], bd[nb * 2], bd[nb * 2 + 1]);
                }
            if (tau_act) {
#pragma unroll
                for (int mb = 0; mb < 2; ++mb)
#pragma unroll
                    for (int nb = 0; nb < 2; ++nb)
                        mma_f16(acct[mb][nb], a[mb], bt[nb * 2], bt[nb * 2 + 1]);
            }
        }
    };

    const uint32_t st0 = data;
    const uint32_t st1 = data + STAGE_BYTES;

    load_chunk(0, st0);

    cp_wait<0>(); __syncthreads();
    load_chunk(1, st1);
    compute(st0, false);          // c=0

    cp_wait<0>(); __syncthreads();
    load_chunk(2, st0);
    compute(st1, true);           // c=1

    cp_wait<0>(); __syncthreads();
    load_chunk(3, st1);
    compute(st0, true);           // c=2

    cp_wait<0>(); __syncthreads();
    load_chunk(4, st0);
    compute(st1, true);           // c=3

    cp_wait<0>(); __syncthreads();
    load_chunk(5, st1);
    compute(st0, true);           // c=4

    cp_wait<0>(); __syncthreads();
    load_chunk(6, st0);
    compute(st1, false);          // c=5

    cp_wait<0>(); __syncthreads();
    // st1 is now idle: prefetch epilogue operands while c=6 MMAs run.
    // h_ltc tile (128 rows x 64 fp32 = 32KB) at st1; bias arrays at st1+32768.
    {
#pragma unroll
        for (int i = 0; i < 4; ++i) {
            int j = tid + i * 512;            // 2048 x 16B
            int row = j >> 4, c16 = j & 15;
            cp16(st1 + j * 16, h_ltc + (size_t)(m0 + row) * HID + n0 + c16 * 4);
        }
        if (tid < 80) {
            int grp = tid >> 4, q = tid & 15;
            const float* srcp = (grp == 0) ? b_gd + n0
                              : (grp == 1) ? b_gd + HID + n0
                              : (grp == 2) ? b_tau + n0
                              : (grp == 3) ? cm + n0
                                           : gleak + n0;
            cp16(st1 + 32768 + grp * 256 + q * 16, srcp + q * 4);
        }
        cp_commit();
    }
    compute(st0, false);          // c=6
    cp_wait<0>(); __syncthreads();

    // ---- fused epilogue (fast math, all operands in smem) ----
    const float* ep_h = reinterpret_cast<const float*>(dptr + STAGE_BYTES);
    const float* ep_b = reinterpret_cast<const float*>(dptr + STAGE_BYTES + 32768);
    const int g  = lane >> 2;
    const int c2 = (lane & 3) * 2;
#pragma unroll
    for (int mb = 0; mb < 2; ++mb)
#pragma unroll
        for (int nb = 0; nb < 2; ++nb) {
            const int nl = wn + nb * 8 + c2;          // 0..63
            const int n  = n0 + nl;
            const float bg0 = ep_b[nl],        bg1 = ep_b[nl + 1];
            const float bd0 = ep_b[64 + nl],   bd1 = ep_b[64 + nl + 1];
            const float bt0 = ep_b[128 + nl],  bt1 = ep_b[128 + nl + 1];
            const float dc0 = softplus_fast(ep_b[192 + nl])     + softplus_fast(ep_b[256 + nl])     + 1e-6f;
            const float dc1 = softplus_fast(ep_b[192 + nl + 1]) + softplus_fast(ep_b[256 + nl + 1]) + 1e-6f;
#pragma unroll
            for (int h = 0; h < 2; ++h) {
                const int ml = wm + mb * 16 + h * 8 + g;   // 0..127
                const int m  = m0 + ml;
                const float2 hl = *reinterpret_cast<const float2*>(&ep_h[ml * 64 + nl]);

                float gate0 = accg[mb][nb][h * 2 + 0] + bg0;
                float gate1 = accg[mb][nb][h * 2 + 1] + bg1;
                float dyn0  = accd[mb][nb][h * 2 + 0] + bd0;
                float dyn1  = accd[mb][nb][h * 2 + 1] + bd1;
                float tau0  = softplus_fast(acct[mb][nb][h * 2 + 0] + bt0);
                float tau1  = softplus_fast(acct[mb][nb][h * 2 + 1] + bt1);

                float r0 = __fdividef(sigmoid_fast(gate0) * tanh_fast(dyn0) - hl.x, tau0 + dc0);
                float r1 = __fdividef(sigmoid_fast(gate1) * tanh_fast(dyn1) - hl.y, tau1 + dc1);

                float2 o; o.x = r0; o.y = r1;
                *reinterpret_cast<float2*>(&out[(size_t)m * HID + n]) = o;
            }
        }
}

extern "C" void kernel_launch(void* const* d_in, const int* in_sizes, int n_in,
                              void* d_out, int out_size)
{
    // input order: t, h_ltc, x_t, context, W_gd, b_gd, W_tau, b_tau, gleak, cm
    const float* h_ltc   = (const float*)d_in[1];
    const float* x_t     = (const float*)d_in[2];
    const float* context = (const float*)d_in[3];
    const float* W_gd    = (const float*)d_in[4];
    const float* b_gd    = (const float*)d_in[5];
    const float* W_tau   = (const float*)d_in[6];
    const float* b_tau   = (const float*)d_in[7];
    const float* gleak   = (const float*)d_in[8];
    const float* cm      = (const float*)d_in[9];
    float* out = (float*)d_out;

    cudaFuncSetAttribute(ltc_f16_kernel,
                         cudaFuncAttributeMaxDynamicSharedMemorySize, SMEM_DYN);

    prep_all<<<7744, 256>>>(h_ltc, x_t, context, W_gd, W_tau);

    dim3 grid(HID / BN, BROWS / BM);   // (8, 128)
    ltc_f16_kernel<<<grid, NTH, SMEM_DYN>>>(h_ltc, b_gd, b_tau, gleak, cm, out);
}